// round 8
// baseline (speedup 1.0000x reference)
#include <cuda_runtime.h>
#include <math.h>

// OnlineNeuron: T=4 two-compartment SNN recurrence, elementwise, f32.
// Pure HBM-streaming: 256 MB read + 256 MB write, irreducible.
// FINAL (converged R7): one float4 per thread, four timestep LDG.128s
// front-batched (per-thread MLP=4), register-resident recurrence, four
// back-batched STG.128s. block=512, grid=8192, 34 regs.
// Wall floor ~82 us = ~6.25 TB/s sustained mixed R/W stream (machine
// roofline). Falsified levers: MLP>4 (R3), 256-bit ld/st (R4), persistent
// single-wave grid + SW pipeline (R5), block size (R6), cache hints (R7).

#define T_STEPS 4

__device__ __forceinline__ float sigmoidf_(float v) {
    return 1.0f / (1.0f + expf(-v));
}

__global__ __launch_bounds__(512)
void online_neuron_kernel(const float4* __restrict__ x,
                          const float* __restrict__ alpha1,
                          const float* __restrict__ beta1,
                          const float* __restrict__ alpha2,
                          const float* __restrict__ beta2,
                          float4* __restrict__ out,
                          int n4)   // float4 count per timestep slab
{
    int i = blockIdx.x * blockDim.x + threadIdx.x;
    if (i >= n4) return;

    const long long stride = (long long)n4;   // float4 units between timesteps

    // ---- Front-batched loads: 4 independent LDG.128 in flight (MLP=4) ----
    float4 xt[T_STEPS];
    #pragma unroll
    for (int t = 0; t < T_STEPS; t++)
        xt[t] = x[(long long)t * stride + i];

    const float a1 = sigmoidf_(__ldg(alpha1)) - 0.5f;
    const float b1 = sigmoidf_(__ldg(beta1))  - 0.5f;
    const float a2 = sigmoidf_(__ldg(alpha2)) + 0.5f;
    const float b2 = sigmoidf_(__ldg(beta2))  + 0.5f;

    float4 vd = make_float4(0.f, 0.f, 0.f, 0.f);
    float4 vs = make_float4(0.5f, 0.5f, 0.5f, 0.5f);

    float4 o[T_STEPS];

    #pragma unroll
    for (int t = 0; t < T_STEPS; t++) {
        vd.x = a1 * vd.x + b1 * vs.x + xt[t].x;
        vd.y = a1 * vd.y + b1 * vs.y + xt[t].y;
        vd.z = a1 * vd.z + b1 * vs.z + xt[t].z;
        vd.w = a1 * vd.w + b1 * vs.w + xt[t].w;

        vs.x = a2 * vs.x + b2 * vd.x;
        vs.y = a2 * vs.y + b2 * vd.y;
        vs.z = a2 * vs.z + b2 * vd.z;
        vs.w = a2 * vs.w + b2 * vd.w;

        o[t].x = (vs.x >= 1.0f) ? 1.0f : 0.0f;
        o[t].y = (vs.y >= 1.0f) ? 1.0f : 0.0f;
        o[t].z = (vs.z >= 1.0f) ? 1.0f : 0.0f;
        o[t].w = (vs.w >= 1.0f) ? 1.0f : 0.0f;

        vs.x -= o[t].x;  vs.y -= o[t].y;  vs.z -= o[t].z;  vs.w -= o[t].w;
    }

    // ---- Back-batched stores ----
    #pragma unroll
    for (int t = 0; t < T_STEPS; t++)
        out[(long long)t * stride + i] = o[t];
}

extern "C" void kernel_launch(void* const* d_in, const int* in_sizes, int n_in,
                              void* d_out, int out_size)
{
    const float* x      = (const float*)d_in[0];
    const float* alpha1 = (const float*)d_in[1];
    const float* beta1  = (const float*)d_in[2];
    const float* alpha2 = (const float*)d_in[3];
    const float* beta2  = (const float*)d_in[4];
    float* out = (float*)d_out;

    const int n_total = in_sizes[0];          // 512*128*32*32 = 67,108,864
    const int n_slab  = n_total / T_STEPS;    // 16,777,216 floats per slab
    const int n4      = n_slab / 4;           // 4,194,304 float4 per slab

    const int block = 512;
    const int grid  = (n4 + block - 1) / block;   // 8192

    online_neuron_kernel<<<grid, block>>>(
        (const float4*)x, alpha1, beta1, alpha2, beta2, (float4*)out, n4);
}